// round 5
// baseline (speedup 1.0000x reference)
#include <cuda_runtime.h>
#include <cstdint>
#include <cstddef>

// Problem constants
#define B_  4
#define S_  1024
#define D_  256
#define H_  512          // 2*D
#define NT_ 20
#define NS_ 50
#define MROWS (B_*S_*NS_)   // 204800

// ---------------- scratch (static device memory; no allocation) ----------------
__device__ float g_hv[B_*S_*H_];      // hidden_vec = [pe | temb], 8 MB
__device__ float g_hidden[B_*S_*H_];  // aggregated hidden, then LN'd in place, 8 MB
__device__ float g_c[B_*S_*H_];       // hidden_ln @ w_in.T, 8 MB
__device__ float g_as[B_*S_], g_bs[B_*S_], g_ag[B_*S_], g_bg[B_*S_];
__device__ float g_part[(size_t)MROWS*4]; // per-row partials (2 used)
__device__ __align__(16) unsigned short g_wnb[512*512]; // w_noise as bf16, row-major

// ---------------- helpers ----------------
__device__ __forceinline__ float softplus_f(float x) {
    return fmaxf(x, 0.f) + log1pf(expf(-fabsf(x)));
}
__device__ __forceinline__ unsigned f2tf(float f) {
    unsigned u; asm("cvt.rna.tf32.f32 %0, %1;" : "=r"(u) : "f"(f)); return u;
}
// pack two fp32 -> bf16x2 register, lo = first arg
__device__ __forceinline__ unsigned pk_bf(float lo, float hi) {
    unsigned r; asm("cvt.rn.bf16x2.f32 %0, %1, %2;" : "=r"(r) : "f"(hi), "f"(lo)); return r;
}
__device__ __forceinline__ void mma_tf32(float c[4],
        unsigned a0, unsigned a1, unsigned a2, unsigned a3,
        unsigned b0, unsigned b1) {
    asm volatile("mma.sync.aligned.m16n8k8.row.col.f32.tf32.tf32.f32 "
        "{%0,%1,%2,%3}, {%4,%5,%6,%7}, {%8,%9}, {%0,%1,%2,%3};\n"
        : "+f"(c[0]), "+f"(c[1]), "+f"(c[2]), "+f"(c[3])
        : "r"(a0), "r"(a1), "r"(a2), "r"(a3), "r"(b0), "r"(b1));
}
__device__ __forceinline__ void mma_bf16(float c[4],
        unsigned a0, unsigned a1, unsigned a2, unsigned a3,
        unsigned b0, unsigned b1) {
    asm volatile("mma.sync.aligned.m16n8k16.row.col.f32.bf16.bf16.f32 "
        "{%0,%1,%2,%3}, {%4,%5,%6,%7}, {%8,%9}, {%0,%1,%2,%3};\n"
        : "+f"(c[0]), "+f"(c[1]), "+f"(c[2]), "+f"(c[3])
        : "r"(a0), "r"(a1), "r"(a2), "r"(a3), "r"(b0), "r"(b1));
}
__device__ __forceinline__ void cp16(void* smem, const void* g) {
    unsigned s = (unsigned)__cvta_generic_to_shared(smem);
    asm volatile("cp.async.cg.shared.global [%0], [%1], 16;" :: "r"(s), "l"(g));
}
__device__ __forceinline__ void cp_commit() {
    asm volatile("cp.async.commit_group;");
}

// ================= K0: w_noise fp32 -> bf16 row-major pre-pass =================
__global__ void k0_cvt(const float* __restrict__ w)
{
    int i = blockIdx.x * 256 + threadIdx.x;        // < 65536, 4 elems each
    float4 v = *(const float4*)&w[(size_t)i * 4];
    uint2 p;
    p.x = pk_bf(v.x, v.y);
    p.y = pk_bf(v.z, v.w);
    *(uint2*)&g_wnb[(size_t)i * 4] = p;
}

// ================= K1: embeddings + per-event scalar projections =================
__global__ void k1_embed(const int* __restrict__ etype, const float* __restrict__ etime,
                         const float* __restrict__ wt, const float* __restrict__ table,
                         const float* __restrict__ w_sigma, const float* __restrict__ w_gate)
{
    int r = blockIdx.x;            // b*S + s
    int s = r & (S_ - 1);
    int t = threadIdx.x;           // 0..255
    int et = etype[r];
    float tm = etime[r];
    float temb = table[et * D_ + t];

    if (t < 128) {
        float dt = expf((float)(2 * t) * (-9.210340371976184f / (float)D_));
        float arg = (float)s * dt + tm * wt[t];
        g_hv[(size_t)r * H_ + t]       = sinf(arg);
        g_hv[(size_t)r * H_ + 128 + t] = cosf(arg);
    }
    g_hv[(size_t)r * H_ + 256 + t] = temb;

    float pas = temb * w_sigma[t];
    float pbs = temb * w_sigma[D_ + t];
    float pag = temb * w_gate[t];
    float pbg = temb * w_gate[D_ + t];
    __shared__ float red[8][4];
    #pragma unroll
    for (int o = 16; o > 0; o >>= 1) {
        pas += __shfl_xor_sync(0xffffffffu, pas, o);
        pbs += __shfl_xor_sync(0xffffffffu, pbs, o);
        pag += __shfl_xor_sync(0xffffffffu, pag, o);
        pbg += __shfl_xor_sync(0xffffffffu, pbg, o);
    }
    if ((t & 31) == 0) {
        red[t >> 5][0] = pas; red[t >> 5][1] = pbs;
        red[t >> 5][2] = pag; red[t >> 5][3] = pbg;
    }
    __syncthreads();
    if (t == 0) {
        float a = 0, b = 0, c = 0, d = 0;
        #pragma unroll
        for (int i = 0; i < 8; i++) { a += red[i][0]; b += red[i][1]; c += red[i][2]; d += red[i][3]; }
        g_as[r] = a; g_bs[r] = b; g_ag[r] = c; g_bg[r] = d;
    }
}

// ================= K2: fused score generation + triangular aggregation =================
__global__ __launch_bounds__(256) void k2_agg(const float* __restrict__ etime)
{
    __shared__ float Ss[32][64];    // [k][m] scores
    __shared__ float Hs[32][128];   // [k][n] hidden_vec tile
    __shared__ float iT[64], iBS[64], iBG[64];

    int b  = blockIdx.z;
    int i0 = blockIdx.y * 64;
    int h0 = blockIdx.x * 128;
    int t  = threadIdx.x;
    int tx = t & 15, ty = t >> 4;

    if (t < 64) {
        int i = b * S_ + i0 + t;
        iT[t] = etime[i]; iBS[t] = g_bs[i]; iBG[t] = g_bg[i];
    }

    float acc[4][8];
    #pragma unroll
    for (int mi = 0; mi < 4; mi++)
        #pragma unroll
        for (int ni = 0; ni < 8; ni++) acc[mi][ni] = 0.f;

    int jend = i0 + 64;  // strict lower triangular: j < i <= i0+63
    for (int jt = 0; jt < jend; jt += 32) {
        __syncthreads();
        {
            int k = t >> 3;
            int j = jt + k;
            int jg = b * S_ + j;
            float tj = etime[jg], asj = g_as[jg], agj = g_ag[jg];
            int m0 = (t & 7) * 8;
            #pragma unroll
            for (int mm = 0; mm < 8; mm++) {
                int m = m0 + mm;
                float sc = 0.f;
                if (j < i0 + m) {
                    float xs = asj + iBS[m];
                    float sp = softplus_f(xs);
                    float xg = agj + iBG[m];
                    float gt = 1.f / (1.f + expf(-xg));
                    float td = fabsf(tj - iT[m]);
                    sc = gt * expf(-sp * td);
                }
                Ss[k][m] = sc;
            }
        }
        #pragma unroll
        for (int p = 0; p < 4; p++) {
            int rw = p * 8 + (t >> 5);
            int c4 = t & 31;
            *(float4*)&Hs[rw][c4 * 4] =
                *(const float4*)&g_hv[((size_t)(b * S_ + jt + rw)) * H_ + h0 + c4 * 4];
        }
        __syncthreads();
        #pragma unroll
        for (int k = 0; k < 32; k++) {
            float a[4], bb[8];
            *(float4*)a        = *(const float4*)&Ss[k][ty * 4];
            *(float4*)&bb[0]   = *(const float4*)&Hs[k][tx * 8];
            *(float4*)&bb[4]   = *(const float4*)&Hs[k][tx * 8 + 4];
            #pragma unroll
            for (int mi = 0; mi < 4; mi++)
                #pragma unroll
                for (int ni = 0; ni < 8; ni++)
                    acc[mi][ni] = fmaf(a[mi], bb[ni], acc[mi][ni]);
        }
    }
    #pragma unroll
    for (int mi = 0; mi < 4; mi++) {
        int i = i0 + ty * 4 + mi;
        float4 v0 = make_float4(acc[mi][0], acc[mi][1], acc[mi][2], acc[mi][3]);
        float4 v1 = make_float4(acc[mi][4], acc[mi][5], acc[mi][6], acc[mi][7]);
        size_t base = ((size_t)(b * S_ + i)) * H_ + h0 + tx * 8;
        *(float4*)&g_hidden[base]     = v0;
        *(float4*)&g_hidden[base + 4] = v1;
    }
}

// ================= K3: LayerNorm (in place) + mark_probs =================
__global__ void k3_ln_mark(const float* __restrict__ gamma, const float* __restrict__ beta,
                           const float* __restrict__ wpred, float* __restrict__ out)
{
    __shared__ float row[512];
    __shared__ float sred[8];
    __shared__ float logits[24];
    int r = blockIdx.x, t = threadIdx.x;
    int wid = t >> 5, lane = t & 31;

    float x0 = g_hidden[(size_t)r * H_ + t];
    float x1 = g_hidden[(size_t)r * H_ + 256 + t];

    float v = x0 + x1;
    #pragma unroll
    for (int o = 16; o > 0; o >>= 1) v += __shfl_xor_sync(0xffffffffu, v, o);
    if (lane == 0) sred[wid] = v;
    __syncthreads();
    if (t == 0) { float s = 0; for (int i = 0; i < 8; i++) s += sred[i]; sred[0] = s * (1.f / 512.f); }
    __syncthreads();
    float mu = sred[0];
    __syncthreads();

    float d0 = x0 - mu, d1 = x1 - mu;
    v = d0 * d0 + d1 * d1;
    #pragma unroll
    for (int o = 16; o > 0; o >>= 1) v += __shfl_xor_sync(0xffffffffu, v, o);
    if (lane == 0) sred[wid] = v;
    __syncthreads();
    if (t == 0) { float s = 0; for (int i = 0; i < 8; i++) s += sred[i]; sred[0] = s * (1.f / 512.f); }
    __syncthreads();
    float inv = rsqrtf(sred[0] + 1e-6f);

    float y0 = d0 * inv * gamma[t]       + beta[t];
    float y1 = d1 * inv * gamma[256 + t] + beta[256 + t];
    g_hidden[(size_t)r * H_ + t]       = y0;
    g_hidden[(size_t)r * H_ + 256 + t] = y1;
    row[t] = y0; row[256 + t] = y1;
    __syncthreads();

    #pragma unroll
    for (int q = 0; q < 3; q++) {
        int j = wid + 8 * q;
        if (j < NT_) {
            float p = 0.f;
            for (int i = lane; i < 512; i += 32) p += row[i] * wpred[j * 512 + i];
            #pragma unroll
            for (int o = 16; o > 0; o >>= 1) p += __shfl_xor_sync(0xffffffffu, p, o);
            if (lane == 0) logits[j] = p;
        }
    }
    __syncthreads();
    if (t == 0) {
        float mx = logits[0];
        for (int j = 1; j < NT_; j++) mx = fmaxf(mx, logits[j]);
        float e[NT_]; float s = 0.f;
        for (int j = 0; j < NT_; j++) { e[j] = expf(logits[j] - mx); s += e[j]; }
        float is = 1.f / s;
        for (int j = 0; j < NT_; j++) out[B_ * S_ + r * NT_ + j] = e[j] * is;
    }
}

// ---------------- K4 machinery: 128x128 tile, BK=16, 2-stage cp.async, tf32 ----
#define BKp 20

__device__ __forceinline__ void stage_load(float (*dst)[BKp], const float* __restrict__ src,
                                           int m0, int kt, int t)
{
    #pragma unroll
    for (int p = 0; p < 2; p++) {
        int q = t + p * 256;
        int row = q >> 2, c4 = q & 3;
        cp16(&dst[row][c4 * 4], &src[(size_t)(m0 + row) * 512 + kt + c4 * 4]);
    }
}

__device__ __forceinline__ void tile_mma(const float (*As)[BKp], const float (*Bs)[BKp],
                                         float acc[4][4][4], int mw, int nw, int g, int tig)
{
    #pragma unroll
    for (int kk = 0; kk < 16; kk += 8) {
        unsigned a[4][4], bfrag[4][2];
        #pragma unroll
        for (int mt = 0; mt < 4; mt++) {
            int rw = mw * 64 + mt * 16 + g;
            a[mt][0] = f2tf(As[rw][kk + tig]);     a[mt][1] = f2tf(As[rw + 8][kk + tig]);
            a[mt][2] = f2tf(As[rw][kk + tig + 4]); a[mt][3] = f2tf(As[rw + 8][kk + tig + 4]);
        }
        #pragma unroll
        for (int nt = 0; nt < 4; nt++) {
            int cl = nw * 32 + nt * 8 + g;
            bfrag[nt][0] = f2tf(Bs[cl][kk + tig]);
            bfrag[nt][1] = f2tf(Bs[cl][kk + tig + 4]);
        }
        #pragma unroll
        for (int mt = 0; mt < 4; mt++)
            #pragma unroll
            for (int nt = 0; nt < 4; nt++)
                mma_tf32(acc[mt][nt], a[mt][0], a[mt][1], a[mt][2], a[mt][3],
                         bfrag[nt][0], bfrag[nt][1]);
    }
}

// ================= K4: c = hidden_ln @ w_in.T  (tf32, 2-stage cp.async) =================
__global__ __launch_bounds__(256) void k4_cgemm(const float* __restrict__ W)
{
    __shared__ float As[2][128][BKp];
    __shared__ float Bs[2][128][BKp];
    int t = threadIdx.x;
    int n0 = blockIdx.x * 128;
    int m0 = blockIdx.y * 128;
    int wid = t >> 5, lane = t & 31;
    int mw = wid >> 2, nw = wid & 3;
    int g = lane >> 2, tig = lane & 3;

    float acc[4][4][4];
    #pragma unroll
    for (int a = 0; a < 4; a++)
        #pragma unroll
        for (int b = 0; b < 4; b++)
            #pragma unroll
            for (int c = 0; c < 4; c++) acc[a][b][c] = 0.f;

    stage_load(As[0], g_hidden, m0, 0, t);
    stage_load(Bs[0], W, n0, 0, t);
    cp_commit();

    for (int it = 0; it < 32; ++it) {
        int buf = it & 1;
        if (it < 31) {
            stage_load(As[buf ^ 1], g_hidden, m0, (it + 1) * 16, t);
            stage_load(Bs[buf ^ 1], W, n0, (it + 1) * 16, t);
            cp_commit();
            asm volatile("cp.async.wait_group 1;");
        } else {
            asm volatile("cp.async.wait_group 0;");
        }
        __syncthreads();
        tile_mma(As[buf], Bs[buf], acc, mw, nw, g, tig);
        __syncthreads();
    }

    #pragma unroll
    for (int mt = 0; mt < 4; mt++) {
        int r0 = m0 + mw * 64 + mt * 16 + g;
        #pragma unroll
        for (int nt = 0; nt < 4; nt++) {
            int col = n0 + nw * 32 + nt * 8 + tig * 2;
            *(float2*)&g_c[(size_t)r0 * 512 + col]       = make_float2(acc[mt][nt][0], acc[mt][nt][1]);
            *(float2*)&g_c[(size_t)(r0 + 8) * 512 + col] = make_float2(acc[mt][nt][2], acc[mt][nt][3]);
        }
    }
}

// ================= K5: relu(noise@Wn^T + c) . w_time partials =================
// bf16 m16n8k16, CTA 128(M)x256(N), BK=32, 512 threads.
// smem bf16 tiles, 64 B/row; 8B-unit swizzle u_phys = u_log ^ ((row&2)<<1)
// (= 16B chunk c_phys = c_log ^ (row&2); no intra-chunk swap).
// A: LDG fp32 -> cvt -> STS double buffer.  B: raw bf16 via cp.async (from g_wnb).
// Layout: A[buf] at sm + buf*8192 (128x64B); B[buf] at sm + 16384 + buf*16384 (256x64B).
__global__ __launch_bounds__(512, 1) void k5_noise(const float* __restrict__ An,
                                                   const float* __restrict__ wtime)
{
    __shared__ __align__(16) char sm[49152];
    int t = threadIdx.x;
    int n0 = blockIdx.x * 256;
    int m0 = blockIdx.y * 128;

    // ---- A staging mapping: thread -> (row, physical 16B chunk) ----
    int ar = t >> 2, acq = t & 3;
    int am = acq ^ (ar & 2);                       // logical chunk (8 fp32 cols)
    const float* agp = An + (size_t)(m0 + ar) * 512 + am * 8;
    char* asts = sm + ar * 64 + acq * 16;

    // ---- B staging mapping (cp.async): thread -> (row, 2 physical chunks) ----
    int brw = t >> 1;
    int bc0 = (t & 1) * 2;
    const char* bgbase = (const char*)g_wnb + (size_t)(n0 + brw) * 1024;  // 512 bf16/row
    char* bsts = sm + 16384 + brw * 64;

    // ---- compute mapping ----
    int wid = t >> 5, lane = t & 31;
    int mw = wid >> 3, nw = wid & 7;               // 2 x 8 warps, warp tile 64x32
    int g = lane >> 2, tig = lane & 3;
    int sw = (g & 2) << 1;                         // fragment swizzle (bit 2 only)

    float acc[4][4][4];
    #pragma unroll
    for (int a = 0; a < 4; a++)
        #pragma unroll
        for (int b = 0; b < 4; b++)
            #pragma unroll
            for (int c = 0; c < 4; c++) acc[a][b][c] = 0.f;

    float4 a0f, a1f;

    // ---- prologue: A(0) ldg+sts, B(0) cp.async ----
    a0f = *(const float4*)(agp);
    a1f = *(const float4*)(agp + 4);
    {
        uint4 pa;
        pa.x = pk_bf(a0f.x, a0f.y); pa.y = pk_bf(a0f.z, a0f.w);
        pa.z = pk_bf(a1f.x, a1f.y); pa.w = pk_bf(a1f.z, a1f.w);
        *(uint4*)(asts) = pa;
    }
    #pragma unroll
    for (int c = 0; c < 2; c++) {
        int pc = bc0 + c;
        int m = pc ^ (brw & 2);
        cp16(bsts + pc * 16, bgbase + m * 16);
    }
    cp_commit();

    for (int it = 0; it < 16; ++it) {
        int buf = it & 1;
        if (it < 15) {                              // A prefetch into regs
            a0f = *(const float4*)(agp + (it + 1) * 32);
            a1f = *(const float4*)(agp + (it + 1) * 32 + 4);
        }
        asm volatile("cp.async.wait_group 0;");     // B(buf) complete (this thread)
        __syncthreads();                            // all threads' tiles ready
        if (it < 15) {                              // B(it+1) into buf^1 (post-barrier: safe)
            int ktb = (it + 1) * 64;                // byte offset along K (32 bf16)
            #pragma unroll
            for (int c = 0; c < 2; c++) {
                int pc = bc0 + c;
                int m = pc ^ (brw & 2);
                cp16(bsts + (buf ^ 1) * 16384 + pc * 16, bgbase + ktb + m * 16);
            }
            cp_commit();
        }
        // ---- compute on buf ----
        const uint2* A2 = (const uint2*)(sm + buf * 8192);
        const uint2* B2 = (const uint2*)(sm + 16384 + buf * 16384);
        #pragma unroll
        for (int ks = 0; ks < 2; ks++) {
            int up = (tig + 4 * ks) ^ sw;           // swizzled 8B unit
            unsigned bfr[4][2];
            #pragma unroll
            for (int nt = 0; nt < 4; nt++) {
                int cl = nw * 32 + nt * 8 + g;
                uint2 v = B2[cl * 8 + up];
                bfr[nt][0] = v.x; bfr[nt][1] = v.y;
            }
            #pragma unroll
            for (int mt = 0; mt < 4; mt++) {
                int rw = mw * 64 + mt * 16 + g;
                uint2 va = A2[rw * 8 + up];
                uint2 vb = A2[(rw + 8) * 8 + up];
                #pragma unroll
                for (int nt = 0; nt < 4; nt++)
                    mma_bf16(acc[mt][nt], va.x, vb.x, va.y, vb.y, bfr[nt][0], bfr[nt][1]);
            }
        }
        if (it < 15) {                              // A(it+1) STS into buf^1
            uint4 pa;
            pa.x = pk_bf(a0f.x, a0f.y); pa.y = pk_bf(a0f.z, a0f.w);
            pa.z = pk_bf(a1f.x, a1f.y); pa.w = pk_bf(a1f.z, a1f.w);
            *(uint4*)(asts + (buf ^ 1) * 8192) = pa;
        }
    }

    // ---- fused epilogue: +bias(c), relu, dot w_time, reduce ----
    float* red = (float*)sm;   // reuses A buf0 region (last read at it=14, pre-sync(15))
    #pragma unroll
    for (int mt = 0; mt < 4; mt++) {
        int lrow  = mw * 64 + mt * 16 + g;
        int grow0 = m0 + lrow;
        int grow1 = grow0 + 8;
        int br0 = grow0 / NS_;
        int br1 = grow1 / NS_;
        float s0 = 0.f, s1 = 0.f;
        #pragma unroll
        for (int nt = 0; nt < 4; nt++) {
            int col = n0 + nw * 32 + nt * 8 + tig * 2;
            float b00 = g_c[(size_t)br0 * 512 + col], b01 = g_c[(size_t)br0 * 512 + col + 1];
            float b10 = g_c[(size_t)br1 * 512 + col], b11 = g_c[(size_t)br1 * 512 + col + 1];
            float w0 = __ldg(&wtime[col]), w1 = __ldg(&wtime[col + 1]);
            s0 += fmaxf(acc[mt][nt][0] + b00, 0.f) * w0;
            s0 += fmaxf(acc[mt][nt][1] + b01, 0.f) * w1;
            s1 += fmaxf(acc[mt][nt][2] + b10, 0.f) * w0;
            s1 += fmaxf(acc[mt][nt][3] + b11, 0.f) * w1;
        }
        s0 += __shfl_xor_sync(0xffffffffu, s0, 1);
        s0 += __shfl_xor_sync(0xffffffffu, s0, 2);
        s1 += __shfl_xor_sync(0xffffffffu, s1, 1);
        s1 += __shfl_xor_sync(0xffffffffu, s1, 2);
        if (tig == 0) { red[lrow * 8 + nw] = s0; red[(lrow + 8) * 8 + nw] = s1; }
    }
    __syncthreads();
    if (t < 128) {
        float p = 0.f;
        #pragma unroll
        for (int q = 0; q < 8; q++) p += red[t * 8 + q];
        g_part[(size_t)(m0 + t) * 2 + blockIdx.x] = p;
    }
}

// ================= K6: pred_time = mean_n softplus(sum of 2 partials) =================
__global__ void k6_pred(float* __restrict__ out)
{
    int idx = blockIdx.x * 128 + threadIdx.x;   // b*S+s, < 4096
    const float2* p = (const float2*)&g_part[(size_t)idx * NS_ * 2];
    float accum = 0.f;
    #pragma unroll 5
    for (int n = 0; n < NS_; n++) {
        float2 v = p[n];
        accum += softplus_f(v.x + v.y);
    }
    out[idx] = accum * (1.f / (float)NS_);
}

// ================= launch =================
extern "C" void kernel_launch(void* const* d_in, const int* in_sizes, int n_in,
                              void* d_out, int out_size)
{
    const int*   etype   = (const int*)  d_in[0];
    const float* etime   = (const float*)d_in[1];
    const float* noise   = (const float*)d_in[2];
    const float* wt      = (const float*)d_in[3];
    const float* table   = (const float*)d_in[4];
    const float* w_sigma = (const float*)d_in[5];
    const float* w_gate  = (const float*)d_in[6];
    const float* ln_g    = (const float*)d_in[7];
    const float* ln_b    = (const float*)d_in[8];
    const float* w_pred  = (const float*)d_in[9];
    const float* w_in    = (const float*)d_in[10];
    const float* w_noise = (const float*)d_in[11];
    const float* w_time  = (const float*)d_in[12];
    float* out = (float*)d_out;

    k0_cvt<<<256, 256>>>(w_noise);
    k1_embed<<<B_ * S_, 256>>>(etype, etime, wt, table, w_sigma, w_gate);
    k2_agg<<<dim3(H_ / 128, S_ / 64, B_), 256>>>(etime);
    k3_ln_mark<<<B_ * S_, 256>>>(ln_g, ln_b, w_pred, out);
    k4_cgemm<<<dim3(4, (B_ * S_) / 128), 256>>>(w_in);
    k5_noise<<<dim3(2, MROWS / 128), 512>>>(noise, w_time);
    k6_pred<<<(B_ * S_) / 128, 128>>>(out);
}

// round 17
// speedup vs baseline: 1.2464x; 1.2464x over previous
#include <cuda_runtime.h>
#include <cstdint>
#include <cstddef>

// Problem constants
#define B_  4
#define S_  1024
#define D_  256
#define H_  512          // 2*D
#define NT_ 20
#define NS_ 50
#define MROWS (B_*S_*NS_)   // 204800

// ---------------- scratch (static device memory; no allocation) ----------------
__device__ float g_hv[B_*S_*H_];      // hidden_vec = [pe | temb], 8 MB
__device__ float g_hidden[B_*S_*H_];  // aggregated hidden, then LN'd in place, 8 MB
__device__ float g_c[B_*S_*H_];       // hidden_ln @ w_in.T, 8 MB
__device__ float g_scores[(size_t)B_*S_*S_]; // 16 MB, lower-tri tiles valid, diag-tile zeros
__device__ float g_as[B_*S_], g_bs[B_*S_], g_ag[B_*S_], g_bg[B_*S_];
__device__ float g_part[(size_t)MROWS*4]; // per-row partials (2 used)
__device__ __align__(16) unsigned short g_wnb[512*512]; // w_noise as bf16, row-major

// ---------------- helpers ----------------
__device__ __forceinline__ float softplus_f(float x) {
    return fmaxf(x, 0.f) + log1pf(expf(-fabsf(x)));
}
__device__ __forceinline__ unsigned f2tf(float f) {
    unsigned u; asm("cvt.rna.tf32.f32 %0, %1;" : "=r"(u) : "f"(f)); return u;
}
// pack two fp32 -> bf16x2 register, lo = first arg
__device__ __forceinline__ unsigned pk_bf(float lo, float hi) {
    unsigned r; asm("cvt.rn.bf16x2.f32 %0, %1, %2;" : "=r"(r) : "f"(hi), "f"(lo)); return r;
}
__device__ __forceinline__ void mma_tf32(float c[4],
        unsigned a0, unsigned a1, unsigned a2, unsigned a3,
        unsigned b0, unsigned b1) {
    asm volatile("mma.sync.aligned.m16n8k8.row.col.f32.tf32.tf32.f32 "
        "{%0,%1,%2,%3}, {%4,%5,%6,%7}, {%8,%9}, {%0,%1,%2,%3};\n"
        : "+f"(c[0]), "+f"(c[1]), "+f"(c[2]), "+f"(c[3])
        : "r"(a0), "r"(a1), "r"(a2), "r"(a3), "r"(b0), "r"(b1));
}
__device__ __forceinline__ void mma_bf16(float c[4],
        unsigned a0, unsigned a1, unsigned a2, unsigned a3,
        unsigned b0, unsigned b1) {
    asm volatile("mma.sync.aligned.m16n8k16.row.col.f32.bf16.bf16.f32 "
        "{%0,%1,%2,%3}, {%4,%5,%6,%7}, {%8,%9}, {%0,%1,%2,%3};\n"
        : "+f"(c[0]), "+f"(c[1]), "+f"(c[2]), "+f"(c[3])
        : "r"(a0), "r"(a1), "r"(a2), "r"(a3), "r"(b0), "r"(b1));
}
__device__ __forceinline__ void cp16(void* smem, const void* g) {
    unsigned s = (unsigned)__cvta_generic_to_shared(smem);
    asm volatile("cp.async.cg.shared.global [%0], [%1], 16;" :: "r"(s), "l"(g));
}
__device__ __forceinline__ void cp_commit() {
    asm volatile("cp.async.commit_group;");
}

// ================= K0: w_noise fp32 -> bf16 row-major pre-pass =================
__global__ void k0_cvt(const float* __restrict__ w)
{
    int i = blockIdx.x * 256 + threadIdx.x;        // < 65536, 4 elems each
    float4 v = *(const float4*)&w[(size_t)i * 4];
    uint2 p;
    p.x = pk_bf(v.x, v.y);
    p.y = pk_bf(v.z, v.w);
    *(uint2*)&g_wnb[(size_t)i * 4] = p;
}

// ================= K1: embeddings + per-event scalar projections =================
__global__ void k1_embed(const int* __restrict__ etype, const float* __restrict__ etime,
                         const float* __restrict__ wt, const float* __restrict__ table,
                         const float* __restrict__ w_sigma, const float* __restrict__ w_gate)
{
    int r = blockIdx.x;            // b*S + s
    int s = r & (S_ - 1);
    int t = threadIdx.x;           // 0..255
    int et = etype[r];
    float tm = etime[r];
    float temb = table[et * D_ + t];

    if (t < 128) {
        float dt = expf((float)(2 * t) * (-9.210340371976184f / (float)D_));
        float arg = (float)s * dt + tm * wt[t];
        g_hv[(size_t)r * H_ + t]       = sinf(arg);
        g_hv[(size_t)r * H_ + 128 + t] = cosf(arg);
    }
    g_hv[(size_t)r * H_ + 256 + t] = temb;

    float pas = temb * w_sigma[t];
    float pbs = temb * w_sigma[D_ + t];
    float pag = temb * w_gate[t];
    float pbg = temb * w_gate[D_ + t];
    __shared__ float red[8][4];
    #pragma unroll
    for (int o = 16; o > 0; o >>= 1) {
        pas += __shfl_xor_sync(0xffffffffu, pas, o);
        pbs += __shfl_xor_sync(0xffffffffu, pbs, o);
        pag += __shfl_xor_sync(0xffffffffu, pag, o);
        pbg += __shfl_xor_sync(0xffffffffu, pbg, o);
    }
    if ((t & 31) == 0) {
        red[t >> 5][0] = pas; red[t >> 5][1] = pbs;
        red[t >> 5][2] = pag; red[t >> 5][3] = pbg;
    }
    __syncthreads();
    if (t == 0) {
        float a = 0, b = 0, c = 0, d = 0;
        #pragma unroll
        for (int i = 0; i < 8; i++) { a += red[i][0]; b += red[i][1]; c += red[i][2]; d += red[i][3]; }
        g_as[r] = a; g_bs[r] = b; g_ag[r] = c; g_bg[r] = d;
    }
}

// ================= K2a: score tiles (computed ONCE), lower-tri only =================
__global__ __launch_bounds__(256) void k2a_score(const float* __restrict__ etime)
{
    int b  = blockIdx.z;
    int i0 = blockIdx.y * 128;
    int j0 = blockIdx.x * 128;
    if (j0 > i0) return;                    // tile never read by K2b

    __shared__ float iT[128], iBS[128], iBG[128];
    __shared__ float jT[128], jAS[128], jAG[128];
    int t = threadIdx.x;
    if (t < 128) {
        int ig = b * S_ + i0 + t;
        iT[t] = etime[ig]; iBS[t] = g_bs[ig]; iBG[t] = g_bg[ig];
    } else {
        int jg = b * S_ + j0 + (t - 128);
        jT[t-128] = etime[jg]; jAS[t-128] = g_as[jg]; jAG[t-128] = g_ag[jg];
    }
    __syncthreads();

    int i = t >> 1;                         // 0..127
    int jb = (t & 1) * 64;                  // j half
    int gi = i0 + i;
    float ti = iT[i], bsi = iBS[i], bgi = iBG[i];
    float* orow = &g_scores[((size_t)b * S_ + gi) * S_ + j0 + jb];

    #pragma unroll 4
    for (int jj = 0; jj < 64; jj += 4) {
        float v[4];
        #pragma unroll
        for (int q = 0; q < 4; q++) {
            int j = jb + jj + q;
            float sc = 0.f;
            if (j0 + j < gi) {
                float sp = softplus_f(jAS[j] + bsi);
                float gt = 1.f / (1.f + expf(-(jAG[j] + bgi)));
                sc = gt * expf(-sp * fabsf(jT[j] - ti));
            }
            v[q] = sc;
        }
        *(float4*)&orow[jj] = make_float4(v[0], v[1], v[2], v[3]);
    }
}

// ================= K2b: hidden = scores @ hv (triangular tf32 tensor GEMM) =========
#define BKp 20
__global__ __launch_bounds__(256) void k2b_agg()
{
    __shared__ float As[2][128][BKp];
    __shared__ float Bs[2][16][132];
    int t  = threadIdx.x;
    int b  = blockIdx.z;
    int n0 = blockIdx.x * 128;
    int m0 = blockIdx.y * 128;
    const float* Abase = g_scores + (size_t)b * S_ * S_;
    const float* Bbase = g_hv + (size_t)b * S_ * H_;
    int wid = t >> 5, lane = t & 31;
    int mw = wid >> 2, nw = wid & 3;
    int g = lane >> 2, tig = lane & 3;

    float acc[4][4][4];
    #pragma unroll
    for (int a = 0; a < 4; a++)
        #pragma unroll
        for (int bb = 0; bb < 4; bb++)
            #pragma unroll
            for (int c = 0; c < 4; c++) acc[a][bb][c] = 0.f;

    int niter = (m0 + 128) / 16;            // triangular: k runs to i-tile top

    #define K2B_STAGE(buf, kt) do { \
        _Pragma("unroll") \
        for (int p = 0; p < 2; p++) { \
            int q = t + p * 256; \
            int row = q >> 2, c4 = q & 3; \
            cp16(&As[buf][row][c4 * 4], Abase + (size_t)(m0 + row) * S_ + (kt) + c4 * 4); \
        } \
        _Pragma("unroll") \
        for (int p = 0; p < 2; p++) { \
            int q = t + p * 256; \
            int row = q >> 5, c = q & 31; \
            cp16(&Bs[buf][row][c * 4], Bbase + (size_t)((kt) + row) * H_ + n0 + c * 4); \
        } \
        cp_commit(); \
    } while (0)

    K2B_STAGE(0, 0);

    for (int it = 0; it < niter; ++it) {
        int buf = it & 1;
        if (it < niter - 1) {
            K2B_STAGE(buf ^ 1, (it + 1) * 16);
            asm volatile("cp.async.wait_group 1;");
        } else {
            asm volatile("cp.async.wait_group 0;");
        }
        __syncthreads();
        #pragma unroll
        for (int kk = 0; kk < 16; kk += 8) {
            unsigned a[4][4], bfrag[4][2];
            #pragma unroll
            for (int mt = 0; mt < 4; mt++) {
                int rw = mw * 64 + mt * 16 + g;
                a[mt][0] = f2tf(As[buf][rw][kk + tig]);     a[mt][1] = f2tf(As[buf][rw + 8][kk + tig]);
                a[mt][2] = f2tf(As[buf][rw][kk + tig + 4]); a[mt][3] = f2tf(As[buf][rw + 8][kk + tig + 4]);
            }
            #pragma unroll
            for (int nt = 0; nt < 4; nt++) {
                int cl = nw * 32 + nt * 8 + g;
                bfrag[nt][0] = f2tf(Bs[buf][kk + tig][cl]);
                bfrag[nt][1] = f2tf(Bs[buf][kk + tig + 4][cl]);
            }
            #pragma unroll
            for (int mt = 0; mt < 4; mt++)
                #pragma unroll
                for (int nt = 0; nt < 4; nt++)
                    mma_tf32(acc[mt][nt], a[mt][0], a[mt][1], a[mt][2], a[mt][3],
                             bfrag[nt][0], bfrag[nt][1]);
        }
        __syncthreads();
    }
    #undef K2B_STAGE

    #pragma unroll
    for (int mt = 0; mt < 4; mt++) {
        int r0 = b * S_ + m0 + mw * 64 + mt * 16 + g;
        #pragma unroll
        for (int nt = 0; nt < 4; nt++) {
            int col = n0 + nw * 32 + nt * 8 + tig * 2;
            *(float2*)&g_hidden[(size_t)r0 * H_ + col]       = make_float2(acc[mt][nt][0], acc[mt][nt][1]);
            *(float2*)&g_hidden[(size_t)(r0 + 8) * H_ + col] = make_float2(acc[mt][nt][2], acc[mt][nt][3]);
        }
    }
}

// ================= K3: LayerNorm (in place) + mark_probs =================
__global__ void k3_ln_mark(const float* __restrict__ gamma, const float* __restrict__ beta,
                           const float* __restrict__ wpred, float* __restrict__ out)
{
    __shared__ float row[512];
    __shared__ float sred[8];
    __shared__ float logits[24];
    int r = blockIdx.x, t = threadIdx.x;
    int wid = t >> 5, lane = t & 31;

    float x0 = g_hidden[(size_t)r * H_ + t];
    float x1 = g_hidden[(size_t)r * H_ + 256 + t];

    float v = x0 + x1;
    #pragma unroll
    for (int o = 16; o > 0; o >>= 1) v += __shfl_xor_sync(0xffffffffu, v, o);
    if (lane == 0) sred[wid] = v;
    __syncthreads();
    if (t == 0) { float s = 0; for (int i = 0; i < 8; i++) s += sred[i]; sred[0] = s * (1.f / 512.f); }
    __syncthreads();
    float mu = sred[0];
    __syncthreads();

    float d0 = x0 - mu, d1 = x1 - mu;
    v = d0 * d0 + d1 * d1;
    #pragma unroll
    for (int o = 16; o > 0; o >>= 1) v += __shfl_xor_sync(0xffffffffu, v, o);
    if (lane == 0) sred[wid] = v;
    __syncthreads();
    if (t == 0) { float s = 0; for (int i = 0; i < 8; i++) s += sred[i]; sred[0] = s * (1.f / 512.f); }
    __syncthreads();
    float inv = rsqrtf(sred[0] + 1e-6f);

    float y0 = d0 * inv * gamma[t]       + beta[t];
    float y1 = d1 * inv * gamma[256 + t] + beta[256 + t];
    g_hidden[(size_t)r * H_ + t]       = y0;
    g_hidden[(size_t)r * H_ + 256 + t] = y1;
    row[t] = y0; row[256 + t] = y1;
    __syncthreads();

    #pragma unroll
    for (int q = 0; q < 3; q++) {
        int j = wid + 8 * q;
        if (j < NT_) {
            float p = 0.f;
            for (int i = lane; i < 512; i += 32) p += row[i] * wpred[j * 512 + i];
            #pragma unroll
            for (int o = 16; o > 0; o >>= 1) p += __shfl_xor_sync(0xffffffffu, p, o);
            if (lane == 0) logits[j] = p;
        }
    }
    __syncthreads();
    if (t == 0) {
        float mx = logits[0];
        for (int j = 1; j < NT_; j++) mx = fmaxf(mx, logits[j]);
        float e[NT_]; float s = 0.f;
        for (int j = 0; j < NT_; j++) { e[j] = expf(logits[j] - mx); s += e[j]; }
        float is = 1.f / s;
        for (int j = 0; j < NT_; j++) out[B_ * S_ + r * NT_ + j] = e[j] * is;
    }
}

// ---------------- K4 machinery ----
__device__ __forceinline__ void stage_load(float (*dst)[BKp], const float* __restrict__ src,
                                           int m0, int kt, int t)
{
    #pragma unroll
    for (int p = 0; p < 2; p++) {
        int q = t + p * 256;
        int row = q >> 2, c4 = q & 3;
        cp16(&dst[row][c4 * 4], &src[(size_t)(m0 + row) * 512 + kt + c4 * 4]);
    }
}

__device__ __forceinline__ void tile_mma(const float (*As)[BKp], const float (*Bs)[BKp],
                                         float acc[4][4][4], int mw, int nw, int g, int tig)
{
    #pragma unroll
    for (int kk = 0; kk < 16; kk += 8) {
        unsigned a[4][4], bfrag[4][2];
        #pragma unroll
        for (int mt = 0; mt < 4; mt++) {
            int rw = mw * 64 + mt * 16 + g;
            a[mt][0] = f2tf(As[rw][kk + tig]);     a[mt][1] = f2tf(As[rw + 8][kk + tig]);
            a[mt][2] = f2tf(As[rw][kk + tig + 4]); a[mt][3] = f2tf(As[rw + 8][kk + tig + 4]);
        }
        #pragma unroll
        for (int nt = 0; nt < 4; nt++) {
            int cl = nw * 32 + nt * 8 + g;
            bfrag[nt][0] = f2tf(Bs[cl][kk + tig]);
            bfrag[nt][1] = f2tf(Bs[cl][kk + tig + 4]);
        }
        #pragma unroll
        for (int mt = 0; mt < 4; mt++)
            #pragma unroll
            for (int nt = 0; nt < 4; nt++)
                mma_tf32(acc[mt][nt], a[mt][0], a[mt][1], a[mt][2], a[mt][3],
                         bfrag[nt][0], bfrag[nt][1]);
    }
}

// ================= K4: c = hidden_ln @ w_in.T  (tf32, 2-stage cp.async) =================
__global__ __launch_bounds__(256) void k4_cgemm(const float* __restrict__ W)
{
    __shared__ float As[2][128][BKp];
    __shared__ float Bs[2][128][BKp];
    int t = threadIdx.x;
    int n0 = blockIdx.x * 128;
    int m0 = blockIdx.y * 128;
    int wid = t >> 5, lane = t & 31;
    int mw = wid >> 2, nw = wid & 3;
    int g = lane >> 2, tig = lane & 3;

    float acc[4][4][4];
    #pragma unroll
    for (int a = 0; a < 4; a++)
        #pragma unroll
        for (int b = 0; b < 4; b++)
            #pragma unroll
            for (int c = 0; c < 4; c++) acc[a][b][c] = 0.f;

    stage_load(As[0], g_hidden, m0, 0, t);
    stage_load(Bs[0], W, n0, 0, t);
    cp_commit();

    for (int it = 0; it < 32; ++it) {
        int buf = it & 1;
        if (it < 31) {
            stage_load(As[buf ^ 1], g_hidden, m0, (it + 1) * 16, t);
            stage_load(Bs[buf ^ 1], W, n0, (it + 1) * 16, t);
            cp_commit();
            asm volatile("cp.async.wait_group 1;");
        } else {
            asm volatile("cp.async.wait_group 0;");
        }
        __syncthreads();
        tile_mma(As[buf], Bs[buf], acc, mw, nw, g, tig);
        __syncthreads();
    }

    #pragma unroll
    for (int mt = 0; mt < 4; mt++) {
        int r0 = m0 + mw * 64 + mt * 16 + g;
        #pragma unroll
        for (int nt = 0; nt < 4; nt++) {
            int col = n0 + nw * 32 + nt * 8 + tig * 2;
            *(float2*)&g_c[(size_t)r0 * 512 + col]       = make_float2(acc[mt][nt][0], acc[mt][nt][1]);
            *(float2*)&g_c[(size_t)(r0 + 8) * 512 + col] = make_float2(acc[mt][nt][2], acc[mt][nt][3]);
        }
    }
}

// ================= K5: relu(noise@Wn^T + c) . w_time partials =================
// bf16 m16n8k16, CTA 128(M)x256(N), BK=32, 512 threads.
// smem bf16 tiles, 64 B/row; 8B-unit swizzle u_phys = u_log ^ ((row&2)<<1)
// (= 16B chunk c_phys = c_log ^ (row&2); no intra-chunk swap).
// A: LDG fp32 -> cvt -> STS double buffer.  B: raw bf16 via cp.async (from g_wnb).
// Layout: A[buf] at sm + buf*8192 (128x64B); B[buf] at sm + 16384 + buf*16384 (256x64B).
__global__ __launch_bounds__(512, 1) void k5_noise(const float* __restrict__ An,
                                                   const float* __restrict__ wtime)
{
    __shared__ __align__(16) char sm[49152];
    int t = threadIdx.x;
    int n0 = blockIdx.x * 256;
    int m0 = blockIdx.y * 128;

    // ---- A staging mapping: thread -> (row, physical 16B chunk) ----
    int ar = t >> 2, acq = t & 3;
    int am = acq ^ (ar & 2);                       // logical chunk (8 fp32 cols)
    const float* agp = An + (size_t)(m0 + ar) * 512 + am * 8;
    char* asts = sm + ar * 64 + acq * 16;

    // ---- B staging mapping (cp.async): thread -> (row, 2 physical chunks) ----
    int brw = t >> 1;
    int bc0 = (t & 1) * 2;
    const char* bgbase = (const char*)g_wnb + (size_t)(n0 + brw) * 1024;  // 512 bf16/row
    char* bsts = sm + 16384 + brw * 64;

    // ---- compute mapping ----
    int wid = t >> 5, lane = t & 31;
    int mw = wid >> 3, nw = wid & 7;               // 2 x 8 warps, warp tile 64x32
    int g = lane >> 2, tig = lane & 3;
    int sw = (g & 2) << 1;                         // fragment swizzle (bit 2 only)

    float acc[4][4][4];
    #pragma unroll
    for (int a = 0; a < 4; a++)
        #pragma unroll
        for (int b = 0; b < 4; b++)
            #pragma unroll
            for (int c = 0; c < 4; c++) acc[a][b][c] = 0.f;

    float4 a0f, a1f;

    // ---- prologue: A(0) ldg+sts, B(0) cp.async ----
    a0f = *(const float4*)(agp);
    a1f = *(const float4*)(agp + 4);
    {
        uint4 pa;
        pa.x = pk_bf(a0f.x, a0f.y); pa.y = pk_bf(a0f.z, a0f.w);
        pa.z = pk_bf(a1f.x, a1f.y); pa.w = pk_bf(a1f.z, a1f.w);
        *(uint4*)(asts) = pa;
    }
    #pragma unroll
    for (int c = 0; c < 2; c++) {
        int pc = bc0 + c;
        int m = pc ^ (brw & 2);
        cp16(bsts + pc * 16, bgbase + m * 16);
    }
    cp_commit();

    for (int it = 0; it < 16; ++it) {
        int buf = it & 1;
        if (it < 15) {                              // A prefetch into regs
            a0f = *(const float4*)(agp + (it + 1) * 32);
            a1f = *(const float4*)(agp + (it + 1) * 32 + 4);
        }
        asm volatile("cp.async.wait_group 0;");     // B(buf) complete (this thread)
        __syncthreads();                            // all threads' tiles ready
        if (it < 15) {                              // B(it+1) into buf^1 (post-barrier: safe)
            int ktb = (it + 1) * 64;                // byte offset along K (32 bf16)
            #pragma unroll
            for (int c = 0; c < 2; c++) {
                int pc = bc0 + c;
                int m = pc ^ (brw & 2);
                cp16(bsts + (buf ^ 1) * 16384 + pc * 16, bgbase + ktb + m * 16);
            }
            cp_commit();
        }
        // ---- compute on buf ----
        const uint2* A2 = (const uint2*)(sm + buf * 8192);
        const uint2* B2 = (const uint2*)(sm + 16384 + buf * 16384);
        #pragma unroll
        for (int ks = 0; ks < 2; ks++) {
            int up = (tig + 4 * ks) ^ sw;           // swizzled 8B unit
            unsigned bfr[4][2];
            #pragma unroll
            for (int nt = 0; nt < 4; nt++) {
                int cl = nw * 32 + nt * 8 + g;
                uint2 v = B2[cl * 8 + up];
                bfr[nt][0] = v.x; bfr[nt][1] = v.y;
            }
            #pragma unroll
            for (int mt = 0; mt < 4; mt++) {
                int rw = mw * 64 + mt * 16 + g;
                uint2 va = A2[rw * 8 + up];
                uint2 vb = A2[(rw + 8) * 8 + up];
                #pragma unroll
                for (int nt = 0; nt < 4; nt++)
                    mma_bf16(acc[mt][nt], va.x, vb.x, va.y, vb.y, bfr[nt][0], bfr[nt][1]);
            }
        }
        if (it < 15) {                              // A(it+1) STS into buf^1
            uint4 pa;
            pa.x = pk_bf(a0f.x, a0f.y); pa.y = pk_bf(a0f.z, a0f.w);
            pa.z = pk_bf(a1f.x, a1f.y); pa.w = pk_bf(a1f.z, a1f.w);
            *(uint4*)(asts + (buf ^ 1) * 8192) = pa;
        }
    }

    // ---- fused epilogue: +bias(c), relu, dot w_time, reduce ----
    float* red = (float*)sm;   // reuses A buf0 region (last read at it=14, pre-sync(15))
    #pragma unroll
    for (int mt = 0; mt < 4; mt++) {
        int lrow  = mw * 64 + mt * 16 + g;
        int grow0 = m0 + lrow;
        int grow1 = grow0 + 8;
        int br0 = grow0 / NS_;
        int br1 = grow1 / NS_;
        float s0 = 0.f, s1 = 0.f;
        #pragma unroll
        for (int nt = 0; nt < 4; nt++) {
            int col = n0 + nw * 32 + nt * 8 + tig * 2;
            float b00 = g_c[(size_t)br0 * 512 + col], b01 = g_c[(size_t)br0 * 512 + col + 1];
            float b10 = g_c[(size_t)br1 * 512 + col], b11 = g_c[(size_t)br1 * 512 + col + 1];
            float w0 = __ldg(&wtime[col]), w1 = __ldg(&wtime[col + 1]);
            s0 += fmaxf(acc[mt][nt][0] + b00, 0.f) * w0;
            s0 += fmaxf(acc[mt][nt][1] + b01, 0.f) * w1;
            s1 += fmaxf(acc[mt][nt][2] + b10, 0.f) * w0;
            s1 += fmaxf(acc[mt][nt][3] + b11, 0.f) * w1;
        }
        s0 += __shfl_xor_sync(0xffffffffu, s0, 1);
        s0 += __shfl_xor_sync(0xffffffffu, s0, 2);
        s1 += __shfl_xor_sync(0xffffffffu, s1, 1);
        s1 += __shfl_xor_sync(0xffffffffu, s1, 2);
        if (tig == 0) { red[lrow * 8 + nw] = s0; red[(lrow + 8) * 8 + nw] = s1; }
    }
    __syncthreads();
    if (t < 128) {
        float p = 0.f;
        #pragma unroll
        for (int q = 0; q < 8; q++) p += red[t * 8 + q];
        g_part[(size_t)(m0 + t) * 2 + blockIdx.x] = p;
    }
}

// ================= K6: pred_time = mean_n softplus(sum of 2 partials) =================
__global__ void k6_pred(float* __restrict__ out)
{
    int idx = blockIdx.x * 128 + threadIdx.x;   // b*S+s, < 4096
    const float2* p = (const float2*)&g_part[(size_t)idx * NS_ * 2];
    float accum = 0.f;
    #pragma unroll 5
    for (int n = 0; n < NS_; n++) {
        float2 v = p[n];
        accum += softplus_f(v.x + v.y);
    }
    out[idx] = accum * (1.f / (float)NS_);
}

// ================= launch =================
extern "C" void kernel_launch(void* const* d_in, const int* in_sizes, int n_in,
                              void* d_out, int out_size)
{
    const int*   etype   = (const int*)  d_in[0];
    const float* etime   = (const float*)d_in[1];
    const float* noise   = (const float*)d_in[2];
    const float* wt      = (const float*)d_in[3];
    const float* table   = (const float*)d_in[4];
    const float* w_sigma = (const float*)d_in[5];
    const float* w_gate  = (const float*)d_in[6];
    const float* ln_g    = (const float*)d_in[7];
    const float* ln_b    = (const float*)d_in[8];
    const float* w_pred  = (const float*)d_in[9];
    const float* w_in    = (const float*)d_in[10];
    const float* w_noise = (const float*)d_in[11];
    const float* w_time  = (const float*)d_in[12];
    float* out = (float*)d_out;

    k0_cvt<<<256, 256>>>(w_noise);
    k1_embed<<<B_ * S_, 256>>>(etype, etime, wt, table, w_sigma, w_gate);
    k2a_score<<<dim3(8, 8, B_), 256>>>(etime);
    k2b_agg<<<dim3(4, 8, B_), 256>>>();
    k3_ln_mark<<<B_ * S_, 256>>>(ln_g, ln_b, w_pred, out);
    k4_cgemm<<<dim3(4, (B_ * S_) / 128), 256>>>(w_in);
    k5_noise<<<dim3(2, MROWS / 128), 512>>>(noise, w_time);
    k6_pred<<<(B_ * S_) / 128, 128>>>(out);
}